// round 3
// baseline (speedup 1.0000x reference)
#include <cuda_runtime.h>
#include <cuda_bf16.h>
#include <cstdint>

// Problem dims (fixed by the dataset)
#define MDIM 4096
#define NDIM 4096
#define KDIM 4096

#define BM 128
#define BN 128
#define BK 32        // == MX block size: per-row k-slice of a tile is exactly one block
#define LD 40        // smem row stride in bf16 elements (80B): conflict-free mma reads
#define NKIT (KDIM / BK)

// Exact 2^e for e in [-126, 127] — immune to any fast-math flags.
__device__ __forceinline__ float exp2i(int e) {
    return __uint_as_float((uint32_t)(e + 127) << 23);
}

// RNE onto the signed e2m1 grid {0,.5,1,1.5,2,3,4,6}; matches reference
// searchsorted + ties-to-even on every midpoint (0.25,0.75,...,5.0).
__device__ __forceinline__ float q_e2m1(float v) {
    float mag = fabsf(v);
    float q;
    if (mag <= 2.0f)      q = rintf(mag + mag) * 0.5f;               // step 0.5
    else if (mag < 4.0f)  q = rintf(mag);                            // step 1
    else                  q = fminf(rintf(mag * 0.5f) * 2.0f, 6.0f); // step 2, sat 6
    return copysignf(q, v);
}

// Decode one e2m1 nibble to f32 by direct bit construction (branch-light, exact).
__device__ __forceinline__ float dec_e2m1(uint32_t nib) {
    uint32_t j = nib & 7u;
    uint32_t bits = (j >= 2u) ? (((126u + (j >> 1)) << 23) | ((j & 1u) << 22))
                              : (j * 0x3F000000u);   // j=0 -> 0.0, j=1 -> 0.5
    bits |= (nib & 8u) << 28;                        // sign
    return __uint_as_float(bits);
}

__device__ __forceinline__ uint32_t pack2(float a, float b) {
    return (uint32_t)__bfloat16_as_ushort(__float2bfloat16(a)) |
           ((uint32_t)__bfloat16_as_ushort(__float2bfloat16(b)) << 16);
}

// ---------------------------------------------------------------------------
// Single fused kernel: C[M,N] = qdq_mxfp4(X)[M,K] @ dequant(W)[N,K]^T
// No device-global scratch, no cp.async. Register-prefetch double buffering.
// ---------------------------------------------------------------------------
__global__ __launch_bounds__(256) void fused_kernel(
    const float* __restrict__ X, const int* __restrict__ WP,
    const int* __restrict__ WS, float* __restrict__ C)
{
    __shared__ __nv_bfloat16 sA[2][BM * LD];
    __shared__ __nv_bfloat16 sB[2][BN * LD];

    const int tid  = threadIdx.x;
    const int lane = tid & 31;
    const int warp = tid >> 5;
    const int wm = warp >> 2, wn = warp & 3;   // 2x4 warp grid: 64-row x 32-col
    const int g  = lane >> 2, tg = lane & 3;
    const int bM = blockIdx.y * BM, bN = blockIdx.x * BN;

    // Loader role: thread -> (row, half). Two threads (t, t^1) share one row;
    // each handles 16 consecutive k (half an MX block).
    const int row  = tid >> 1;                 // 0..127
    const int half = tid & 1;                  // k cols [0,16) or [16,32)

    const float* xp  = X  + (size_t)(bM + row) * KDIM + half * 16;
    const int*   wpp = WP + (size_t)(bN + row) * (KDIM / 2) + half * 8;
    const int*   wsp = WS + (size_t)(bN + row) * (KDIM / BK);

    float4 xv0, xv1, xv2, xv3;   // 16 fp32 of x
    int4   wv0, wv1;             // 8 packed weight bytes (one int32 each)
    int    sv;                   // e8m0 scale for this row's current 32-block

    // prefetch kt = 0
    {
        const float4* xq = (const float4*)xp;
        xv0 = xq[0]; xv1 = xq[1]; xv2 = xq[2]; xv3 = xq[3];
        const int4* wq = (const int4*)wpp;
        wv0 = wq[0]; wv1 = wq[1];
        sv  = wsp[0];
    }

    float acc[4][4][4];
    #pragma unroll
    for (int i = 0; i < 4; i++)
        #pragma unroll
        for (int j = 0; j < 4; j++)
            #pragma unroll
            for (int r = 0; r < 4; r++) acc[i][j][r] = 0.0f;

    for (int kt = 0; kt < NKIT; kt++) {
        const int s = kt & 1;

        // ---- A: on-the-fly qdq_mxfp4 (block = this row's 32 k-values) ----
        {
            float f[16] = { xv0.x, xv0.y, xv0.z, xv0.w,
                            xv1.x, xv1.y, xv1.z, xv1.w,
                            xv2.x, xv2.y, xv2.z, xv2.w,
                            xv3.x, xv3.y, xv3.z, xv3.w };
            float m = 0.0f;
            #pragma unroll
            for (int i = 0; i < 16; i++) m = fmaxf(m, fabsf(f[i]));
            m = fmaxf(m, __shfl_xor_sync(0xffffffffu, m, 1));  // partner half
            // floor(log2(m)) from exponent bits; m==0 -> e=-127 -> clamp path
            int e  = ((int)(__float_as_uint(m) >> 23) & 0xFF) - 127;
            int eu = e - 2;                    // F4_E2M1_MAX_POW2
            if (eu < -126) eu = -126;          // ref: scale = max(2^e_unb, 2^-126)
            const float scl = exp2i(eu);
            const float inv = exp2i(-eu);      // exact power-of-two reciprocal
            uint32_t pk[8];
            #pragma unroll
            for (int i = 0; i < 8; i++)
                pk[i] = pack2(q_e2m1(f[2*i]   * inv) * scl,
                              q_e2m1(f[2*i+1] * inv) * scl);
            uint4* dst = (uint4*)&sA[s][row * LD + half * 16];
            dst[0] = make_uint4(pk[0], pk[1], pk[2], pk[3]);
            dst[1] = make_uint4(pk[4], pk[5], pk[6], pk[7]);
        }

        // ---- B: on-the-fly weight dequant (low nibble first) ----
        {
            float bs;
            int ei = sv - 127;                 // e8m0; ws==0 -> 2^-127 exact
            bs = (ei < -126) ? __uint_as_float(0x00400000u) : exp2i(ei);
            int wvv[8] = { wv0.x, wv0.y, wv0.z, wv0.w,
                           wv1.x, wv1.y, wv1.z, wv1.w };
            uint32_t pk[8];
            #pragma unroll
            for (int i = 0; i < 8; i++) {
                uint32_t byte = (uint32_t)wvv[i] & 0xFFu;
                pk[i] = pack2(dec_e2m1(byte & 0xFu) * bs,
                              dec_e2m1((byte >> 4) & 0xFu) * bs);
            }
            uint4* dst = (uint4*)&sB[s][row * LD + half * 16];
            dst[0] = make_uint4(pk[0], pk[1], pk[2], pk[3]);
            dst[1] = make_uint4(pk[4], pk[5], pk[6], pk[7]);
        }

        __syncthreads();   // single barrier per iter (write->read; stage reuse proven safe)

        // ---- prefetch next tile into registers (latency hides under mma) ----
        if (kt + 1 < NKIT) {
            const float4* xq = (const float4*)(xp + (kt + 1) * BK);
            xv0 = xq[0]; xv1 = xq[1]; xv2 = xq[2]; xv3 = xq[3];
            const int4* wq = (const int4*)(wpp + (kt + 1) * 16);
            wv0 = wq[0]; wv1 = wq[1];
            sv  = wsp[kt + 1];
        }

        // ---- mma over stage s ----
        #pragma unroll
        for (int kk = 0; kk < 2; kk++) {       // two k16 steps per BK
            uint32_t a[4][4], b[4][2];
            #pragma unroll
            for (int ti = 0; ti < 4; ti++) {
                const __nv_bfloat16* p = &sA[s][(wm * 64 + ti * 16 + g) * LD + kk * 16 + tg * 2];
                a[ti][0] = *reinterpret_cast<const uint32_t*>(p);
                a[ti][1] = *reinterpret_cast<const uint32_t*>(p + 8 * LD);
                a[ti][2] = *reinterpret_cast<const uint32_t*>(p + 8);
                a[ti][3] = *reinterpret_cast<const uint32_t*>(p + 8 * LD + 8);
            }
            #pragma unroll
            for (int tj = 0; tj < 4; tj++) {
                const __nv_bfloat16* p = &sB[s][(wn * 32 + tj * 8 + g) * LD + kk * 16 + tg * 2];
                b[tj][0] = *reinterpret_cast<const uint32_t*>(p);
                b[tj][1] = *reinterpret_cast<const uint32_t*>(p + 8);
            }
            #pragma unroll
            for (int ti = 0; ti < 4; ti++) {
                #pragma unroll
                for (int tj = 0; tj < 4; tj++) {
                    asm volatile(
                        "mma.sync.aligned.m16n8k16.row.col.f32.bf16.bf16.f32 "
                        "{%0,%1,%2,%3}, {%4,%5,%6,%7}, {%8,%9}, {%0,%1,%2,%3};\n"
                        : "+f"(acc[ti][tj][0]), "+f"(acc[ti][tj][1]),
                          "+f"(acc[ti][tj][2]), "+f"(acc[ti][tj][3])
                        : "r"(a[ti][0]), "r"(a[ti][1]), "r"(a[ti][2]), "r"(a[ti][3]),
                          "r"(b[tj][0]), "r"(b[tj][1]));
                }
            }
        }
    }

    // Epilogue: c0,c1 -> (row g, cols 2tg..), c2,c3 -> (row g+8, same cols)
    #pragma unroll
    for (int ti = 0; ti < 4; ti++) {
        #pragma unroll
        for (int tj = 0; tj < 4; tj++) {
            int r = bM + wm * 64 + ti * 16 + g;
            int c = bN + wn * 32 + tj * 8 + tg * 2;
            float2 lo = make_float2(acc[ti][tj][0], acc[ti][tj][1]);
            float2 hi = make_float2(acc[ti][tj][2], acc[ti][tj][3]);
            *reinterpret_cast<float2*>(&C[(size_t)r * NDIM + c]) = lo;
            *reinterpret_cast<float2*>(&C[(size_t)(r + 8) * NDIM + c]) = hi;
        }
    }
}

// ---------------------------------------------------------------------------
extern "C" void kernel_launch(void* const* d_in, const int* in_sizes, int n_in,
                              void* d_out, int out_size) {
    // Bind by unique element count; fall back to metadata (dict) order.
    const float* x  = nullptr;
    const int*   wp = nullptr;
    const int*   ws = nullptr;
    for (int i = 0; i < n_in; i++) {
        if      (in_sizes[i] == MDIM * KDIM)      x  = (const float*)d_in[i];
        else if (in_sizes[i] == NDIM * KDIM / 2)  wp = (const int*)d_in[i];
        else if (in_sizes[i] == NDIM * KDIM / 32) ws = (const int*)d_in[i];
    }
    if (!x || !wp || !ws) {
        x  = (const float*)d_in[0];
        wp = (const int*)d_in[1];
        ws = (const int*)d_in[2];
    }

    dim3 grid(NDIM / BN, MDIM / BM);
    fused_kernel<<<grid, 256>>>(x, wp, ws, (float*)d_out);
}

// round 4
// speedup vs baseline: 1.7032x; 1.7032x over previous
#include <cuda_runtime.h>
#include <cuda_bf16.h>
#include <cstdint>

// Problem dims (fixed by the dataset)
#define MDIM 4096
#define NDIM 4096
#define KDIM 4096

#define BM 128
#define BN 128
#define BK 32
#define LD 40   // smem row stride in bf16 (80B): ldmatrix rows hit distinct banks
#define NKIT (KDIM / BK)

// Scratch: precomputed bf16 operands (pitfalls.md: __device__ globals are the
// sanctioned scratch path — this round isolates whether they work here).
__device__ __nv_bfloat16 g_xq[(size_t)MDIM * KDIM];   // 32 MB
__device__ __nv_bfloat16 g_w [(size_t)NDIM * KDIM];   // 32 MB

// Exact 2^e for e in [-126, 127] — immune to fast-math.
__device__ __forceinline__ float exp2i(int e) {
    return __uint_as_float((uint32_t)(e + 127) << 23);
}

// RNE onto signed e2m1 grid {0,.5,1,1.5,2,3,4,6}; matches reference ties-to-even.
__device__ __forceinline__ float q_e2m1(float v) {
    float mag = fabsf(v);
    float q;
    if (mag <= 2.0f)      q = rintf(mag + mag) * 0.5f;
    else if (mag < 4.0f)  q = rintf(mag);
    else                  q = fminf(rintf(mag * 0.5f) * 2.0f, 6.0f);
    return copysignf(q, v);
}

__device__ __forceinline__ float dec_e2m1(uint32_t nib) {
    uint32_t j = nib & 7u;
    uint32_t bits = (j >= 2u) ? (((126u + (j >> 1)) << 23) | ((j & 1u) << 22))
                              : (j * 0x3F000000u);
    bits |= (nib & 8u) << 28;
    return __uint_as_float(bits);
}

__device__ __forceinline__ uint32_t pack2(float a, float b) {
    return (uint32_t)__bfloat16_as_ushort(__float2bfloat16(a)) |
           ((uint32_t)__bfloat16_as_ushort(__float2bfloat16(b)) << 16);
}

// ---------------------------------------------------------------------------
// Kernel 1: qdq_mxfp4(x) -> bf16. Thread = 16 els; pair (t, t^1) = one 32-block.
// (Exactly the R3 fused A-path, proven correct.)
// ---------------------------------------------------------------------------
__global__ void qdq_x_kernel(const float* __restrict__ X) {
    size_t t = (size_t)blockIdx.x * blockDim.x + threadIdx.x;
    const float4* xq = (const float4*)(X + 16 * t);
    float4 xv0 = xq[0], xv1 = xq[1], xv2 = xq[2], xv3 = xq[3];
    float f[16] = { xv0.x, xv0.y, xv0.z, xv0.w, xv1.x, xv1.y, xv1.z, xv1.w,
                    xv2.x, xv2.y, xv2.z, xv2.w, xv3.x, xv3.y, xv3.z, xv3.w };
    float m = 0.0f;
    #pragma unroll
    for (int i = 0; i < 16; i++) m = fmaxf(m, fabsf(f[i]));
    m = fmaxf(m, __shfl_xor_sync(0xffffffffu, m, 1));   // partner half-block

    int e  = ((int)(__float_as_uint(m) >> 23) & 0xFF) - 127;
    int eu = e - 2;
    if (eu < -126) eu = -126;
    const float scl = exp2i(eu);
    const float inv = exp2i(-eu);

    uint32_t pk[8];
    #pragma unroll
    for (int i = 0; i < 8; i++)
        pk[i] = pack2(q_e2m1(f[2*i] * inv) * scl, q_e2m1(f[2*i+1] * inv) * scl);
    uint4* dst = (uint4*)(g_xq + 16 * t);
    dst[0] = make_uint4(pk[0], pk[1], pk[2], pk[3]);
    dst[1] = make_uint4(pk[4], pk[5], pk[6], pk[7]);
}

// ---------------------------------------------------------------------------
// Kernel 2: dequant W -> bf16. Thread = 16 values (8 packed bytes, half a block).
// (Exactly the R3 fused B-path, proven correct.)
// ---------------------------------------------------------------------------
__global__ void wdq_kernel(const int* __restrict__ WP, const int* __restrict__ WS) {
    size_t t = (size_t)blockIdx.x * blockDim.x + threadIdx.x;
    const int4* wq = (const int4*)(WP + 8 * t);
    int4 wv0 = wq[0], wv1 = wq[1];
    int sv = WS[t >> 1];

    int ei = sv - 127;
    float bs = (ei < -126) ? __uint_as_float(0x00400000u) : exp2i(ei);
    int wvv[8] = { wv0.x, wv0.y, wv0.z, wv0.w, wv1.x, wv1.y, wv1.z, wv1.w };
    uint32_t pk[8];
    #pragma unroll
    for (int i = 0; i < 8; i++) {
        uint32_t byte = (uint32_t)wvv[i] & 0xFFu;
        pk[i] = pack2(dec_e2m1(byte & 0xFu) * bs, dec_e2m1((byte >> 4) & 0xFu) * bs);
    }
    uint4* dst = (uint4*)(g_w + 16 * t);
    dst[0] = make_uint4(pk[0], pk[1], pk[2], pk[3]);
    dst[1] = make_uint4(pk[4], pk[5], pk[6], pk[7]);
}

// ---------------------------------------------------------------------------
// Kernel 3: GEMM. R3's proven skeleton (reg-prefetch double buffer, single
// barrier/iter) minus convert, plus ldmatrix fragment loads.
// ---------------------------------------------------------------------------
__device__ __forceinline__ void ldsm_x4(uint32_t* r, uint32_t addr) {
    asm volatile("ldmatrix.sync.aligned.m8n8.x4.shared.b16 {%0,%1,%2,%3}, [%4];"
                 : "=r"(r[0]), "=r"(r[1]), "=r"(r[2]), "=r"(r[3]) : "r"(addr));
}
__device__ __forceinline__ void ldsm_x2(uint32_t* r, uint32_t addr) {
    asm volatile("ldmatrix.sync.aligned.m8n8.x2.shared.b16 {%0,%1}, [%2];"
                 : "=r"(r[0]), "=r"(r[1]) : "r"(addr));
}

__global__ __launch_bounds__(256) void gemm_kernel(float* __restrict__ C) {
    __shared__ __nv_bfloat16 sA[2][BM * LD];
    __shared__ __nv_bfloat16 sB[2][BN * LD];

    const int tid  = threadIdx.x;
    const int lane = tid & 31;
    const int warp = tid >> 5;
    const int wm = warp >> 2, wn = warp & 3;       // 2x4 warps: 64-row x 32-col
    const int g  = lane >> 2, tg = lane & 3;
    const int bM = blockIdx.y * BM, bN = blockIdx.x * BN;

    // Loader: pair (t, t^1) covers one row's 32-k slice (16 bf16 = 32B each).
    const int row  = tid >> 1;
    const int half = tid & 1;
    const __nv_bfloat16* ap = g_xq + (size_t)(bM + row) * KDIM + half * 16;
    const __nv_bfloat16* bp = g_w  + (size_t)(bN + row) * KDIM + half * 16;

    // ldmatrix per-lane source coords.
    // A x4 quads: {rows 0-7, k0-7}, {rows 8-15, k0-7}, {rows 0-7, k8-15}, {rows 8-15, k8-15}
    const int rowA = ((lane >> 3) & 1) * 8 + (lane & 7);
    const int colA = (lane >> 4) * 8;
    // B x2: {n 0-7, k0-7}, {n 0-7, k8-15} (lanes 16-31 unused but given valid addrs)
    const int rowB = lane & 7;
    const int colB = ((lane >> 3) & 1) * 8;

    const uint32_t saddrA[2] = {
        (uint32_t)__cvta_generic_to_shared(&sA[0][(wm * 64 + rowA) * LD + colA]),
        (uint32_t)__cvta_generic_to_shared(&sA[1][(wm * 64 + rowA) * LD + colA]) };
    const uint32_t saddrB[2] = {
        (uint32_t)__cvta_generic_to_shared(&sB[0][(wn * 32 + rowB) * LD + colB]),
        (uint32_t)__cvta_generic_to_shared(&sB[1][(wn * 32 + rowB) * LD + colB]) };
    const uint32_t stA = (uint32_t)__cvta_generic_to_shared(&sA[0][row * LD + half * 16])
                       - (uint32_t)__cvta_generic_to_shared(&sA[0][0]);
    const uint32_t stB = stA; // same row/half layout

    uint4 av0, av1, bv0, bv1;
    {   // prefetch kt = 0
        const uint4* aq = (const uint4*)ap;  av0 = aq[0]; av1 = aq[1];
        const uint4* bq = (const uint4*)bp;  bv0 = bq[0]; bv1 = bq[1];
    }

    float acc[4][4][4];
    #pragma unroll
    for (int i = 0; i < 4; i++)
        #pragma unroll
        for (int j = 0; j < 4; j++)
            #pragma unroll
            for (int r = 0; r < 4; r++) acc[i][j][r] = 0.0f;

    for (int kt = 0; kt < NKIT; kt++) {
        const int s = kt & 1;

        {   // stage store
            uint4* da = (uint4*)((char*)sA[s] + stA);  da[0] = av0; da[1] = av1;
            uint4* db = (uint4*)((char*)sB[s] + stB);  db[0] = bv0; db[1] = bv1;
        }
        __syncthreads();   // single barrier per iter (write->read; proven in R3)

        if (kt + 1 < NKIT) {   // prefetch next tile (hides under mma)
            const uint4* aq = (const uint4*)(ap + (kt + 1) * BK);
            av0 = aq[0]; av1 = aq[1];
            const uint4* bq = (const uint4*)(bp + (kt + 1) * BK);
            bv0 = bq[0]; bv1 = bq[1];
        }

        #pragma unroll
        for (int kk = 0; kk < 2; kk++) {
            uint32_t a[4][4], b[4][2];
            #pragma unroll
            for (int ti = 0; ti < 4; ti++)
                ldsm_x4(a[ti], saddrA[s] + (uint32_t)(ti * 16 * LD + kk * 16) * 2u);
            #pragma unroll
            for (int tj = 0; tj < 4; tj++)
                ldsm_x2(b[tj], saddrB[s] + (uint32_t)(tj * 8 * LD + kk * 16) * 2u);
            #pragma unroll
            for (int ti = 0; ti < 4; ti++) {
                #pragma unroll
                for (int tj = 0; tj < 4; tj++) {
                    asm volatile(
                        "mma.sync.aligned.m16n8k16.row.col.f32.bf16.bf16.f32 "
                        "{%0,%1,%2,%3}, {%4,%5,%6,%7}, {%8,%9}, {%0,%1,%2,%3};\n"
                        : "+f"(acc[ti][tj][0]), "+f"(acc[ti][tj][1]),
                          "+f"(acc[ti][tj][2]), "+f"(acc[ti][tj][3])
                        : "r"(a[ti][0]), "r"(a[ti][1]), "r"(a[ti][2]), "r"(a[ti][3]),
                          "r"(b[tj][0]), "r"(b[tj][1]));
                }
            }
        }
        __syncthreads();   // protect stage s from next iteration's overwrite
    }

    #pragma unroll
    for (int ti = 0; ti < 4; ti++) {
        #pragma unroll
        for (int tj = 0; tj < 4; tj++) {
            int r = bM + wm * 64 + ti * 16 + g;
            int c = bN + wn * 32 + tj * 8 + tg * 2;
            float2 lo = make_float2(acc[ti][tj][0], acc[ti][tj][1]);
            float2 hi = make_float2(acc[ti][tj][2], acc[ti][tj][3]);
            *reinterpret_cast<float2*>(&C[(size_t)r * NDIM + c]) = lo;
            *reinterpret_cast<float2*>(&C[(size_t)(r + 8) * NDIM + c]) = hi;
        }
    }
}

// ---------------------------------------------------------------------------
extern "C" void kernel_launch(void* const* d_in, const int* in_sizes, int n_in,
                              void* d_out, int out_size) {
    const float* x  = nullptr;
    const int*   wp = nullptr;
    const int*   ws = nullptr;
    for (int i = 0; i < n_in; i++) {
        if      (in_sizes[i] == MDIM * KDIM)      x  = (const float*)d_in[i];
        else if (in_sizes[i] == NDIM * KDIM / 2)  wp = (const int*)d_in[i];
        else if (in_sizes[i] == NDIM * KDIM / 32) ws = (const int*)d_in[i];
    }
    if (!x || !wp || !ws) {
        x  = (const float*)d_in[0];
        wp = (const int*)d_in[1];
        ws = (const int*)d_in[2];
    }

    // 1) qdq(x): 16.7M els / 16 per thread = 1M threads
    qdq_x_kernel<<<MDIM * (size_t)KDIM / 16 / 256, 256>>>(x);
    // 2) dequant W: 16.7M els / 16 per thread
    wdq_kernel<<<NDIM * (size_t)KDIM / 16 / 256, 256>>>(wp, ws);
    // 3) GEMM
    dim3 grid(NDIM / BN, MDIM / BM);
    gemm_kernel<<<grid, 256>>>((float*)d_out);
}

// round 6
// speedup vs baseline: 2.1915x; 1.2866x over previous
#include <cuda_runtime.h>
#include <cuda_bf16.h>
#include <cstdint>

// Problem dims (fixed by the dataset)
#define MDIM 4096
#define NDIM 4096
#define KDIM 4096

#define BM 128
#define BN 128
#define BK 32
#define LD 40   // smem row stride in bf16 (80B): ldmatrix rows hit distinct banks
#define NKIT (KDIM / BK)

// Scratch: precomputed bf16 operands (proven safe in R4).
__device__ __nv_bfloat16 g_xq[(size_t)MDIM * KDIM];   // 32 MB
__device__ __nv_bfloat16 g_w [(size_t)NDIM * KDIM];   // 32 MB

// Exact 2^e for e in [-126, 127] — immune to fast-math.
__device__ __forceinline__ float exp2i(int e) {
    return __uint_as_float((uint32_t)(e + 127) << 23);
}
__device__ __forceinline__ float q_e2m1(float v) {
    float mag = fabsf(v);
    float q;
    if (mag <= 2.0f)      q = rintf(mag + mag) * 0.5f;
    else if (mag < 4.0f)  q = rintf(mag);
    else                  q = fminf(rintf(mag * 0.5f) * 2.0f, 6.0f);
    return copysignf(q, v);
}
__device__ __forceinline__ float dec_e2m1(uint32_t nib) {
    uint32_t j = nib & 7u;
    uint32_t bits = (j >= 2u) ? (((126u + (j >> 1)) << 23) | ((j & 1u) << 22))
                              : (j * 0x3F000000u);
    bits |= (nib & 8u) << 28;
    return __uint_as_float(bits);
}
__device__ __forceinline__ uint32_t pack2(float a, float b) {
    return (uint32_t)__bfloat16_as_ushort(__float2bfloat16(a)) |
           ((uint32_t)__bfloat16_as_ushort(__float2bfloat16(b)) << 16);
}

// ---------------- Kernel 1: qdq_mxfp4(x) -> bf16 (proven) ----------------
__global__ void qdq_x_kernel(const float* __restrict__ X) {
    size_t t = (size_t)blockIdx.x * blockDim.x + threadIdx.x;
    const float4* xq = (const float4*)(X + 16 * t);
    float4 xv0 = xq[0], xv1 = xq[1], xv2 = xq[2], xv3 = xq[3];
    float f[16] = { xv0.x, xv0.y, xv0.z, xv0.w, xv1.x, xv1.y, xv1.z, xv1.w,
                    xv2.x, xv2.y, xv2.z, xv2.w, xv3.x, xv3.y, xv3.z, xv3.w };
    float m = 0.0f;
    #pragma unroll
    for (int i = 0; i < 16; i++) m = fmaxf(m, fabsf(f[i]));
    m = fmaxf(m, __shfl_xor_sync(0xffffffffu, m, 1));
    int e  = ((int)(__float_as_uint(m) >> 23) & 0xFF) - 127;
    int eu = e - 2;
    if (eu < -126) eu = -126;
    const float scl = exp2i(eu), inv = exp2i(-eu);
    uint32_t pk[8];
    #pragma unroll
    for (int i = 0; i < 8; i++)
        pk[i] = pack2(q_e2m1(f[2*i] * inv) * scl, q_e2m1(f[2*i+1] * inv) * scl);
    uint4* dst = (uint4*)(g_xq + 16 * t);
    dst[0] = make_uint4(pk[0], pk[1], pk[2], pk[3]);
    dst[1] = make_uint4(pk[4], pk[5], pk[6], pk[7]);
}

// ---------------- Kernel 2: dequant W -> bf16 (proven) ----------------
__global__ void wdq_kernel(const int* __restrict__ WP, const int* __restrict__ WS) {
    size_t t = (size_t)blockIdx.x * blockDim.x + threadIdx.x;
    const int4* wq = (const int4*)(WP + 8 * t);
    int4 wv0 = wq[0], wv1 = wq[1];
    int sv = WS[t >> 1];
    int ei = sv - 127;
    float bs = (ei < -126) ? __uint_as_float(0x00400000u) : exp2i(ei);
    int wvv[8] = { wv0.x, wv0.y, wv0.z, wv0.w, wv1.x, wv1.y, wv1.z, wv1.w };
    uint32_t pk[8];
    #pragma unroll
    for (int i = 0; i < 8; i++) {
        uint32_t byte = (uint32_t)wvv[i] & 0xFFu;
        pk[i] = pack2(dec_e2m1(byte & 0xFu) * bs, dec_e2m1((byte >> 4) & 0xFu) * bs);
    }
    uint4* dst = (uint4*)(g_w + 16 * t);
    dst[0] = make_uint4(pk[0], pk[1], pk[2], pk[3]);
    dst[1] = make_uint4(pk[4], pk[5], pk[6], pk[7]);
}

// ---------------- Kernel 3: GEMM (mma.sync; 1 barrier/iter; occ 2) ----------
__device__ __forceinline__ void ldsm_x4(uint32_t* r, uint32_t addr) {
    asm volatile("ldmatrix.sync.aligned.m8n8.x4.shared.b16 {%0,%1,%2,%3}, [%4];"
                 : "=r"(r[0]), "=r"(r[1]), "=r"(r[2]), "=r"(r[3]) : "r"(addr));
}
__device__ __forceinline__ void ldsm_x2(uint32_t* r, uint32_t addr) {
    asm volatile("ldmatrix.sync.aligned.m8n8.x2.shared.b16 {%0,%1}, [%2];"
                 : "=r"(r[0]), "=r"(r[1]) : "r"(addr));
}

__global__ __launch_bounds__(256, 2) void gemm_kernel(float* __restrict__ C) {
    __shared__ __nv_bfloat16 sA[2][BM * LD];
    __shared__ __nv_bfloat16 sB[2][BN * LD];

    const int tid  = threadIdx.x;
    const int lane = tid & 31;
    const int warp = tid >> 5;
    const int wm = warp >> 2, wn = warp & 3;       // 2x4 warps: 64-row x 32-col
    const int g  = lane >> 2, tg = lane & 3;
    const int bM = blockIdx.y * BM, bN = blockIdx.x * BN;

    // Loader: pair (t, t^1) covers one row's 32-k slice (16 bf16 = 32B each).
    const int row  = tid >> 1;
    const int half = tid & 1;
    const __nv_bfloat16* ap = g_xq + (size_t)(bM + row) * KDIM + half * 16;
    const __nv_bfloat16* bp = g_w  + (size_t)(bN + row) * KDIM + half * 16;

    // ldmatrix per-lane source coords (proven in R4).
    const int rowA = ((lane >> 3) & 1) * 8 + (lane & 7);
    const int colA = (lane >> 4) * 8;
    const int rowB = lane & 7;
    const int colB = ((lane >> 3) & 1) * 8;

    const uint32_t saddrA[2] = {
        (uint32_t)__cvta_generic_to_shared(&sA[0][(wm * 64 + rowA) * LD + colA]),
        (uint32_t)__cvta_generic_to_shared(&sA[1][(wm * 64 + rowA) * LD + colA]) };
    const uint32_t saddrB[2] = {
        (uint32_t)__cvta_generic_to_shared(&sB[0][(wn * 32 + rowB) * LD + colB]),
        (uint32_t)__cvta_generic_to_shared(&sB[1][(wn * 32 + rowB) * LD + colB]) };
    const uint32_t stA = (uint32_t)__cvta_generic_to_shared(&sA[0][row * LD + half * 16])
                       - (uint32_t)__cvta_generic_to_shared(&sA[0][0]);
    const uint32_t stB = stA;

    uint4 av0, av1, bv0, bv1;
    {   // prefetch kt = 0
        const uint4* aq = (const uint4*)ap;  av0 = aq[0]; av1 = aq[1];
        const uint4* bq = (const uint4*)bp;  bv0 = bq[0]; bv1 = bq[1];
    }

    float acc[4][4][4];
    #pragma unroll
    for (int i = 0; i < 4; i++)
        #pragma unroll
        for (int j = 0; j < 4; j++)
            #pragma unroll
            for (int r = 0; r < 4; r++) acc[i][j][r] = 0.0f;

    for (int kt = 0; kt < NKIT; kt++) {
        const int s = kt & 1;

        {   // stage store
            uint4* da = (uint4*)((char*)sA[s] + stA);  da[0] = av0; da[1] = av1;
            uint4* db = (uint4*)((char*)sB[s] + stB);  db[0] = bv0; db[1] = bv1;
        }
        // Single barrier per iter: the barrier at iter kt also proves stage s
        // (last read at iter kt-2's mma, before those warps stored at kt-1 and
        // passed barrier kt-1) is safe to overwrite. Two-stage invariant.
        __syncthreads();

        if (kt + 1 < NKIT) {   // prefetch next tile (hides under mma)
            const uint4* aq = (const uint4*)(ap + (kt + 1) * BK);
            av0 = aq[0]; av1 = aq[1];
            const uint4* bq = (const uint4*)(bp + (kt + 1) * BK);
            bv0 = bq[0]; bv1 = bq[1];
        }

        #pragma unroll
        for (int kk = 0; kk < 2; kk++) {
            uint32_t a[4][4], b[4][2];
            #pragma unroll
            for (int ti = 0; ti < 4; ti++)
                ldsm_x4(a[ti], saddrA[s] + (uint32_t)(ti * 16 * LD + kk * 16) * 2u);
            #pragma unroll
            for (int tj = 0; tj < 4; tj++)
                ldsm_x2(b[tj], saddrB[s] + (uint32_t)(tj * 8 * LD + kk * 16) * 2u);
            #pragma unroll
            for (int ti = 0; ti < 4; ti++) {
                #pragma unroll
                for (int tj = 0; tj < 4; tj++) {
                    asm volatile(
                        "mma.sync.aligned.m16n8k16.row.col.f32.bf16.bf16.f32 "
                        "{%0,%1,%2,%3}, {%4,%5,%6,%7}, {%8,%9}, {%0,%1,%2,%3};\n"
                        : "+f"(acc[ti][tj][0]), "+f"(acc[ti][tj][1]),
                          "+f"(acc[ti][tj][2]), "+f"(acc[ti][tj][3])
                        : "r"(a[ti][0]), "r"(a[ti][1]), "r"(a[ti][2]), "r"(a[ti][3]),
                          "r"(b[tj][0]), "r"(b[tj][1]));
                }
            }
        }
    }

    #pragma unroll
    for (int ti = 0; ti < 4; ti++) {
        #pragma unroll
        for (int tj = 0; tj < 4; tj++) {
            int r = bM + wm * 64 + ti * 16 + g;
            int c = bN + wn * 32 + tj * 8 + tg * 2;
            float2 lo = make_float2(acc[ti][tj][0], acc[ti][tj][1]);
            float2 hi = make_float2(acc[ti][tj][2], acc[ti][tj][3]);
            *reinterpret_cast<float2*>(&C[(size_t)r * NDIM + c]) = lo;
            *reinterpret_cast<float2*>(&C[(size_t)(r + 8) * NDIM + c]) = hi;
        }
    }
}

// ---------------------------------------------------------------------------
extern "C" void kernel_launch(void* const* d_in, const int* in_sizes, int n_in,
                              void* d_out, int out_size) {
    const float* x  = nullptr;
    const int*   wp = nullptr;
    const int*   ws = nullptr;
    for (int i = 0; i < n_in; i++) {
        if      (in_sizes[i] == MDIM * KDIM)      x  = (const float*)d_in[i];
        else if (in_sizes[i] == NDIM * KDIM / 2)  wp = (const int*)d_in[i];
        else if (in_sizes[i] == NDIM * KDIM / 32) ws = (const int*)d_in[i];
    }
    if (!x || !wp || !ws) {
        x  = (const float*)d_in[0];
        wp = (const int*)d_in[1];
        ws = (const int*)d_in[2];
    }

    qdq_x_kernel<<<MDIM * (size_t)KDIM / 16 / 256, 256>>>(x);
    wdq_kernel<<<NDIM * (size_t)KDIM / 16 / 256, 256>>>(wp, ws);
    dim3 grid(NDIM / BN, MDIM / BM);
    gemm_kernel<<<grid, 256>>>((float*)d_out);
}

// round 7
// speedup vs baseline: 2.6552x; 1.2116x over previous
#include <cuda_runtime.h>
#include <cuda_bf16.h>
#include <cstdint>

// Problem dims (fixed by the dataset)
#define MDIM 4096
#define NDIM 4096
#define KDIM 4096

#define BM 128
#define BN 256
#define BK 32
#define LD 40   // smem row stride in bf16 (80B): ldmatrix rows hit distinct banks
#define NKIT (KDIM / BK)

#define A_STAGE_B (BM * LD * 2)                 // 10240 B
#define B_STAGE_B (BN * LD * 2)                 // 20480 B
#define SMEM_TOT  (2 * A_STAGE_B + 2 * B_STAGE_B)  // 61440 B (dynamic)

// Scratch: precomputed bf16 operands (proven safe since R4).
__device__ __nv_bfloat16 g_xq[(size_t)MDIM * KDIM];   // 32 MB
__device__ __nv_bfloat16 g_w [(size_t)NDIM * KDIM];   // 32 MB

// Exact 2^e for e in [-126, 127] — immune to fast-math.
__device__ __forceinline__ float exp2i(int e) {
    return __uint_as_float((uint32_t)(e + 127) << 23);
}
__device__ __forceinline__ float q_e2m1(float v) {
    float mag = fabsf(v);
    float q;
    if (mag <= 2.0f)      q = rintf(mag + mag) * 0.5f;
    else if (mag < 4.0f)  q = rintf(mag);
    else                  q = fminf(rintf(mag * 0.5f) * 2.0f, 6.0f);
    return copysignf(q, v);
}
__device__ __forceinline__ float dec_e2m1(uint32_t nib) {
    uint32_t j = nib & 7u;
    uint32_t bits = (j >= 2u) ? (((126u + (j >> 1)) << 23) | ((j & 1u) << 22))
                              : (j * 0x3F000000u);
    bits |= (nib & 8u) << 28;
    return __uint_as_float(bits);
}
__device__ __forceinline__ uint32_t pack2(float a, float b) {
    return (uint32_t)__bfloat16_as_ushort(__float2bfloat16(a)) |
           ((uint32_t)__bfloat16_as_ushort(__float2bfloat16(b)) << 16);
}

// ---------------- Kernel 1: qdq_mxfp4(x) -> bf16 (proven) ----------------
__global__ void qdq_x_kernel(const float* __restrict__ X) {
    size_t t = (size_t)blockIdx.x * blockDim.x + threadIdx.x;
    const float4* xq = (const float4*)(X + 16 * t);
    float4 xv0 = xq[0], xv1 = xq[1], xv2 = xq[2], xv3 = xq[3];
    float f[16] = { xv0.x, xv0.y, xv0.z, xv0.w, xv1.x, xv1.y, xv1.z, xv1.w,
                    xv2.x, xv2.y, xv2.z, xv2.w, xv3.x, xv3.y, xv3.z, xv3.w };
    float m = 0.0f;
    #pragma unroll
    for (int i = 0; i < 16; i++) m = fmaxf(m, fabsf(f[i]));
    m = fmaxf(m, __shfl_xor_sync(0xffffffffu, m, 1));
    int e  = ((int)(__float_as_uint(m) >> 23) & 0xFF) - 127;
    int eu = e - 2;
    if (eu < -126) eu = -126;
    const float scl = exp2i(eu), inv = exp2i(-eu);
    uint32_t pk[8];
    #pragma unroll
    for (int i = 0; i < 8; i++)
        pk[i] = pack2(q_e2m1(f[2*i] * inv) * scl, q_e2m1(f[2*i+1] * inv) * scl);
    uint4* dst = (uint4*)(g_xq + 16 * t);
    dst[0] = make_uint4(pk[0], pk[1], pk[2], pk[3]);
    dst[1] = make_uint4(pk[4], pk[5], pk[6], pk[7]);
}

// ---------------- Kernel 2: dequant W -> bf16 (proven) ----------------
__global__ void wdq_kernel(const int* __restrict__ WP, const int* __restrict__ WS) {
    size_t t = (size_t)blockIdx.x * blockDim.x + threadIdx.x;
    const int4* wq = (const int4*)(WP + 8 * t);
    int4 wv0 = wq[0], wv1 = wq[1];
    int sv = WS[t >> 1];
    int ei = sv - 127;
    float bs = (ei < -126) ? __uint_as_float(0x00400000u) : exp2i(ei);
    int wvv[8] = { wv0.x, wv0.y, wv0.z, wv0.w, wv1.x, wv1.y, wv1.z, wv1.w };
    uint32_t pk[8];
    #pragma unroll
    for (int i = 0; i < 8; i++) {
        uint32_t byte = (uint32_t)wvv[i] & 0xFFu;
        pk[i] = pack2(dec_e2m1(byte & 0xFu) * bs, dec_e2m1((byte >> 4) & 0xFu) * bs);
    }
    uint4* dst = (uint4*)(g_w + 16 * t);
    dst[0] = make_uint4(pk[0], pk[1], pk[2], pk[3]);
    dst[1] = make_uint4(pk[4], pk[5], pk[6], pk[7]);
}

// ---------------- Kernel 3: GEMM 128x256, warp tile 64x64 ----------------
__device__ __forceinline__ void ldsm_x4(uint32_t* r, uint32_t addr) {
    asm volatile("ldmatrix.sync.aligned.m8n8.x4.shared.b16 {%0,%1,%2,%3}, [%4];"
                 : "=r"(r[0]), "=r"(r[1]), "=r"(r[2]), "=r"(r[3]) : "r"(addr));
}

__global__ __launch_bounds__(256, 1) void gemm_kernel(float* __restrict__ C) {
    extern __shared__ __align__(16) char smem[];
    // layout: sA[0], sA[1], sB[0], sB[1]
    __nv_bfloat16* sA0 = (__nv_bfloat16*)smem;
    __nv_bfloat16* sB0 = (__nv_bfloat16*)(smem + 2 * A_STAGE_B);

    const int tid  = threadIdx.x;
    const int lane = tid & 31;
    const int warp = tid >> 5;
    const int wm = warp >> 2, wn = warp & 3;       // 2x4 warps: 64 rows x 64 cols each
    const int g  = lane >> 2, tg = lane & 3;
    const int bM = blockIdx.y * BM, bN = blockIdx.x * BN;

    // ---- global loaders (16B chunks, consecutive tids coalesced) ----
    // A: 512 chunks (2/thread); B: 1024 chunks (4/thread). chunk c -> row c>>2, ch c&3.
    const __nv_bfloat16* Abase = g_xq + (size_t)bM * KDIM;
    const __nv_bfloat16* Bbase = g_w  + (size_t)bN * KDIM;
    uint32_t aoff[2], asw[2], boff[4], bsw[4];
    #pragma unroll
    for (int j = 0; j < 2; j++) {
        int c = tid + j * 256, r = c >> 2, ch = c & 3;
        aoff[j] = r * KDIM + ch * 8;
        asw[j]  = (r * LD + ch * 8) * 2;           // byte offset in stage
    }
    #pragma unroll
    for (int j = 0; j < 4; j++) {
        int c = tid + j * 256, r = c >> 2, ch = c & 3;
        boff[j] = r * KDIM + ch * 8;
        bsw[j]  = (r * LD + ch * 8) * 2;
    }

    // ---- ldmatrix lane coords ----
    // A x4: m0 rows0-7/k0-7, m1 rows8-15/k0-7, m2 rows0-7/k8-15, m3 rows8-15/k8-15
    const int rowA = ((lane >> 3) & 1) * 8 + (lane & 7);
    const int colA = (lane >> 4) * 8;
    // B x4 (two n8 tiles): m0 n0-7/k0-7, m1 n0-7/k8-15, m2 n8-15/k0-7, m3 n8-15/k8-15
    const int rowB = ((lane >> 4) & 1) * 8 + (lane & 7);
    const int colB = ((lane >> 3) & 1) * 8;

    uint32_t saddrA[2], saddrB[2];
    #pragma unroll
    for (int s = 0; s < 2; s++) {
        saddrA[s] = (uint32_t)__cvta_generic_to_shared(
            sA0 + s * (A_STAGE_B / 2) + (wm * 64 + rowA) * LD + colA);
        saddrB[s] = (uint32_t)__cvta_generic_to_shared(
            sB0 + s * (B_STAGE_B / 2) + (wn * 64 + rowB) * LD + colB);
    }

    uint4 av[2], bv[4];
    #pragma unroll
    for (int j = 0; j < 2; j++) av[j] = *(const uint4*)(Abase + aoff[j]);
    #pragma unroll
    for (int j = 0; j < 4; j++) bv[j] = *(const uint4*)(Bbase + boff[j]);

    float acc[4][8][4];
    #pragma unroll
    for (int i = 0; i < 4; i++)
        #pragma unroll
        for (int j = 0; j < 8; j++)
            #pragma unroll
            for (int r = 0; r < 4; r++) acc[i][j][r] = 0.0f;

    for (int kt = 0; kt < NKIT; kt++) {
        const int s = kt & 1;

        {   // stage store
            char* da = smem + s * A_STAGE_B;
            char* db = smem + 2 * A_STAGE_B + s * B_STAGE_B;
            #pragma unroll
            for (int j = 0; j < 2; j++) *(uint4*)(da + asw[j]) = av[j];
            #pragma unroll
            for (int j = 0; j < 4; j++) *(uint4*)(db + bsw[j]) = bv[j];
        }
        // Single barrier per iter; two-stage invariant (proven R6).
        __syncthreads();

        if (kt + 1 < NKIT) {   // prefetch next tile (hides under mma)
            const int k0 = (kt + 1) * BK;
            #pragma unroll
            for (int j = 0; j < 2; j++) av[j] = *(const uint4*)(Abase + aoff[j] + k0);
            #pragma unroll
            for (int j = 0; j < 4; j++) bv[j] = *(const uint4*)(Bbase + boff[j] + k0);
        }

        #pragma unroll
        for (int kk = 0; kk < 2; kk++) {
            uint32_t a[4][4], b[4][4];
            #pragma unroll
            for (int ti = 0; ti < 4; ti++)
                ldsm_x4(a[ti], saddrA[s] + (uint32_t)(ti * 16 * LD + kk * 16) * 2u);
            #pragma unroll
            for (int p = 0; p < 4; p++)     // pair p covers n8-tiles 2p, 2p+1
                ldsm_x4(b[p], saddrB[s] + (uint32_t)(p * 16 * LD + kk * 16) * 2u);
            #pragma unroll
            for (int ti = 0; ti < 4; ti++) {
                #pragma unroll
                for (int tj = 0; tj < 8; tj++) {
                    const int p = tj >> 1, h = (tj & 1) * 2;
                    asm volatile(
                        "mma.sync.aligned.m16n8k16.row.col.f32.bf16.bf16.f32 "
                        "{%0,%1,%2,%3}, {%4,%5,%6,%7}, {%8,%9}, {%0,%1,%2,%3};\n"
                        : "+f"(acc[ti][tj][0]), "+f"(acc[ti][tj][1]),
                          "+f"(acc[ti][tj][2]), "+f"(acc[ti][tj][3])
                        : "r"(a[ti][0]), "r"(a[ti][1]), "r"(a[ti][2]), "r"(a[ti][3]),
                          "r"(b[p][h]), "r"(b[p][h + 1]));
                }
            }
        }
    }

    #pragma unroll
    for (int ti = 0; ti < 4; ti++) {
        #pragma unroll
        for (int tj = 0; tj < 8; tj++) {
            int r = bM + wm * 64 + ti * 16 + g;
            int c = bN + wn * 64 + tj * 8 + tg * 2;
            float2 lo = make_float2(acc[ti][tj][0], acc[ti][tj][1]);
            float2 hi = make_float2(acc[ti][tj][2], acc[ti][tj][3]);
            *reinterpret_cast<float2*>(&C[(size_t)r * NDIM + c]) = lo;
            *reinterpret_cast<float2*>(&C[(size_t)(r + 8) * NDIM + c]) = hi;
        }
    }
}

// ---------------------------------------------------------------------------
extern "C" void kernel_launch(void* const* d_in, const int* in_sizes, int n_in,
                              void* d_out, int out_size) {
    const float* x  = nullptr;
    const int*   wp = nullptr;
    const int*   ws = nullptr;
    for (int i = 0; i < n_in; i++) {
        if      (in_sizes[i] == MDIM * KDIM)      x  = (const float*)d_in[i];
        else if (in_sizes[i] == NDIM * KDIM / 2)  wp = (const int*)d_in[i];
        else if (in_sizes[i] == NDIM * KDIM / 32) ws = (const int*)d_in[i];
    }
    if (!x || !wp || !ws) {
        x  = (const float*)d_in[0];
        wp = (const int*)d_in[1];
        ws = (const int*)d_in[2];
    }

    qdq_x_kernel<<<MDIM * (size_t)KDIM / 16 / 256, 256>>>(x);
    wdq_kernel<<<NDIM * (size_t)KDIM / 16 / 256, 256>>>(wp, ws);

    cudaFuncSetAttribute(gemm_kernel, cudaFuncAttributeMaxDynamicSharedMemorySize, SMEM_TOT);
    dim3 grid(NDIM / BN, MDIM / BM);
    gemm_kernel<<<grid, 256, SMEM_TOT>>>((float*)d_out);
}